// round 5
// baseline (speedup 1.0000x reference)
#include <cuda_runtime.h>
#include <cuda_fp16.h>
#include <cstdint>

// out[n,o] = sum_i x[n,i] * sign(W[o,i]) + b[o],  N=IN=OUT=4096, fp32 in/out.
//
// Legacy HMMA pipe (tcgen05 not emittable: harness PTX target is compute_103).
// Round-4 evidence: f32-accumulate HMMA runs at half rate (tensor pinned at 50%).
// This round: fp16-accumulate MMA chains over K=64 chunks, promoted to fp32
// master accumulators every 2 k-tiles. 128x128x32 CTA tile, 8 warps (64x32),
// 4-stage cp.async pipeline.

#define N_DIM 4096
constexpr int MTILE = 128;
constexpr int NTILE = 128;
constexpr int KTILE = 32;
constexpr int NKT = N_DIM / KTILE;            // 128 (even -> 64 K=64 chunks)
constexpr int S_STRIDE = 40;                  // fp16 elems; 80B rows: conflict-free ldmatrix
constexpr int TILE_ELEMS = 128 * S_STRIDE;    // 5120 fp16
constexpr int STAGE_ELEMS = 2 * TILE_ELEMS;   // A + B
constexpr int SMEM_BYTES = 4 * STAGE_ELEMS * (int)sizeof(__half);  // 81920

__device__ __half g_xh[(size_t)N_DIM * N_DIM];
__device__ __half g_wb[(size_t)N_DIM * N_DIM];

// ---------------------------------------------------------------------------
// prep: binarize W -> fp16, cast x -> fp16
// ---------------------------------------------------------------------------
__global__ void prep_kernel(const float4* __restrict__ x,
                            const float4* __restrict__ W, int n4) {
    int i = blockIdx.x * blockDim.x + threadIdx.x;
    if (i >= n4) return;
    float4 xv = x[i];
    float4 wv = W[i];
    float xs[4] = {xv.x, xv.y, xv.z, xv.w};
    float ws[4] = {wv.x, wv.y, wv.z, wv.w};
    alignas(8) __half xh[4], wb[4];
#pragma unroll
    for (int j = 0; j < 4; j++) {
        xh[j] = __float2half_rn(xs[j]);
        float s = (ws[j] > 0.0f) ? 1.0f : ((ws[j] < 0.0f) ? -1.0f : 0.0f);
        wb[j] = __float2half_rn(s);
    }
    size_t base = (size_t)i * 4;
    *reinterpret_cast<uint2*>(g_xh + base) = *reinterpret_cast<uint2*>(xh);
    *reinterpret_cast<uint2*>(g_wb + base) = *reinterpret_cast<uint2*>(wb);
}

// ---------------------------------------------------------------------------
// PTX helpers
// ---------------------------------------------------------------------------
__device__ __forceinline__ void cp16(uint32_t smem_addr, const void* gmem_ptr) {
    asm volatile("cp.async.cg.shared.global [%0], [%1], 16;\n"
                 :: "r"(smem_addr), "l"(gmem_ptr) : "memory");
}

__device__ __forceinline__ void ldsm_x4(uint32_t* r, uint32_t a) {
    asm volatile("ldmatrix.sync.aligned.m8n8.x4.shared.b16 {%0,%1,%2,%3}, [%4];\n"
                 : "=r"(r[0]), "=r"(r[1]), "=r"(r[2]), "=r"(r[3]) : "r"(a));
}

__device__ __forceinline__ void ldsm_x2(uint32_t* r, uint32_t a) {
    asm volatile("ldmatrix.sync.aligned.m8n8.x2.shared.b16 {%0,%1}, [%2];\n"
                 : "=r"(r[0]), "=r"(r[1]) : "r"(a));
}

// fp16-accumulate MMA: D(f16x2 pair) = A*B + D
__device__ __forceinline__ void mma_h_acc(uint32_t* d, const uint32_t* a,
                                          const uint32_t* b) {
    asm volatile("mma.sync.aligned.m16n8k16.row.col.f16.f16.f16.f16 "
                 "{%0,%1},{%2,%3,%4,%5},{%6,%7},{%0,%1};\n"
                 : "+r"(d[0]), "+r"(d[1])
                 : "r"(a[0]), "r"(a[1]), "r"(a[2]), "r"(a[3]),
                   "r"(b[0]), "r"(b[1]));
}

// fp16-accumulate MMA with C = 0 (chunk start)
__device__ __forceinline__ void mma_h_zero(uint32_t* d, const uint32_t* a,
                                           const uint32_t* b) {
    asm volatile("mma.sync.aligned.m16n8k16.row.col.f16.f16.f16.f16 "
                 "{%0,%1},{%2,%3,%4,%5},{%6,%7},{%8,%8};\n"
                 : "=r"(d[0]), "=r"(d[1])
                 : "r"(a[0]), "r"(a[1]), "r"(a[2]), "r"(a[3]),
                   "r"(b[0]), "r"(b[1]), "r"(0u));
}

// ---------------------------------------------------------------------------
// GEMM: 256 threads = 8 warps, 2(M) x 4(N) warp grid, warp tile 64x32.
// ---------------------------------------------------------------------------
__global__ void __launch_bounds__(256, 1)
gemm_kernel(const float* __restrict__ bias, float* __restrict__ out) {
    extern __shared__ __half smem[];
    const uint32_t smem_base = (uint32_t)__cvta_generic_to_shared(smem);
    const int tid   = threadIdx.x;
    const int lane  = tid & 31;
    const int warp  = tid >> 5;
    const int warpM = warp & 1;
    const int warpN = warp >> 1;
    const int mBase = blockIdx.y * MTILE;
    const int nBase = blockIdx.x * NTILE;

    float acc[4][4][4];          // fp32 master accumulators
    uint32_t hacc[4][4][2];      // fp16x2 chunk accumulators
#pragma unroll
    for (int a = 0; a < 4; a++)
#pragma unroll
        for (int b = 0; b < 4; b++)
#pragma unroll
            for (int c = 0; c < 4; c++) acc[a][b][c] = 0.0f;

    // per-thread cp.async assignment (2 A chunks + 2 B chunks of 16B per k-tile)
    const int r0 = tid >> 2;
    const int r1 = (tid + 256) >> 2;
    const int c0 = (tid & 3) * 8;
    const __half* gA0 = g_xh + (size_t)(mBase + r0) * N_DIM + c0;
    const __half* gA1 = g_xh + (size_t)(mBase + r1) * N_DIM + c0;
    const __half* gB0 = g_wb + (size_t)(nBase + r0) * N_DIM + c0;
    const __half* gB1 = g_wb + (size_t)(nBase + r1) * N_DIM + c0;
    const uint32_t soA0 = (r0 * S_STRIDE + c0) * 2;
    const uint32_t soA1 = (r1 * S_STRIDE + c0) * 2;
    const uint32_t soB0 = soA0 + TILE_ELEMS * 2;
    const uint32_t soB1 = soA1 + TILE_ELEMS * 2;

    auto prefetch = [&](int kt) {
        const uint32_t sb = smem_base + (kt & 3) * (STAGE_ELEMS * 2);
        const int k0 = kt * KTILE;
        cp16(sb + soA0, gA0 + k0);
        cp16(sb + soA1, gA1 + k0);
        cp16(sb + soB0, gB0 + k0);
        cp16(sb + soB1, gB1 + k0);
        asm volatile("cp.async.commit_group;\n" ::: "memory");
    };

    const uint32_t aRow = warpM * 64 + (lane & 15);
    const uint32_t aCol = ((lane >> 4) & 1) * 8;
    const uint32_t aAddr0 = smem_base + (aRow * S_STRIDE + aCol) * 2;
    const uint32_t bRow = warpN * 32 + (lane & 7);
    const uint32_t bCol = ((lane >> 3) & 1) * 8;
    const uint32_t bAddr0 = smem_base + (TILE_ELEMS + bRow * S_STRIDE + bCol) * 2;

    // one k-tile of fp16-acc MMAs; fresh=true zero-starts the chunk accumulators
    auto compute = [&](int s, bool fresh) {
        const uint32_t stOff = (uint32_t)s * (STAGE_ELEMS * 2);
#pragma unroll
        for (int ks = 0; ks < 2; ks++) {
            const uint32_t kOff = ks * 16 * 2;
            uint32_t bf[4][2];
#pragma unroll
            for (int tn = 0; tn < 4; tn++)
                ldsm_x2(bf[tn], bAddr0 + stOff + kOff + tn * (8 * S_STRIDE * 2));
            uint32_t ah[4][4];
#pragma unroll
            for (int tm = 0; tm < 4; tm++)
                ldsm_x4(ah[tm], aAddr0 + stOff + kOff + tm * (16 * S_STRIDE * 2));
            if (fresh && ks == 0) {
#pragma unroll
                for (int tm = 0; tm < 4; tm++)
#pragma unroll
                    for (int tn = 0; tn < 4; tn++)
                        mma_h_zero(hacc[tm][tn], ah[tm], bf[tn]);
            } else {
#pragma unroll
                for (int tm = 0; tm < 4; tm++)
#pragma unroll
                    for (int tn = 0; tn < 4; tn++)
                        mma_h_acc(hacc[tm][tn], ah[tm], bf[tn]);
            }
        }
    };

    // promote fp16 chunk accumulators into fp32 masters
    auto promote = [&]() {
#pragma unroll
        for (int tm = 0; tm < 4; tm++)
#pragma unroll
            for (int tn = 0; tn < 4; tn++) {
                float2 f0 = __half22float2(*reinterpret_cast<__half2*>(&hacc[tm][tn][0]));
                float2 f1 = __half22float2(*reinterpret_cast<__half2*>(&hacc[tm][tn][1]));
                acc[tm][tn][0] += f0.x;
                acc[tm][tn][1] += f0.y;
                acc[tm][tn][2] += f1.x;
                acc[tm][tn][3] += f1.y;
            }
    };

    prefetch(0);
    prefetch(1);
    prefetch(2);

    for (int kt = 0; kt < NKT; kt++) {
        if (kt <= NKT - 3)
            asm volatile("cp.async.wait_group 2;\n" ::: "memory");
        else if (kt == NKT - 2)
            asm volatile("cp.async.wait_group 1;\n" ::: "memory");
        else
            asm volatile("cp.async.wait_group 0;\n" ::: "memory");
        __syncthreads();
        if (kt + 3 < NKT) prefetch(kt + 3);
        compute(kt & 3, (kt & 1) == 0);
        if (kt & 1) promote();   // every 2 k-tiles (K=64 chunk)
    }

    // epilogue: + bias, fp32 store
    const int g  = lane >> 2;
    const int t4 = lane & 3;
    float2 bias2[4];
    int cols[4];
#pragma unroll
    for (int tn = 0; tn < 4; tn++) {
        cols[tn]  = nBase + warpN * 32 + tn * 8 + 2 * t4;
        bias2[tn] = *reinterpret_cast<const float2*>(bias + cols[tn]);
    }
#pragma unroll
    for (int tm = 0; tm < 4; tm++) {
        int rr = mBase + warpM * 64 + tm * 16 + g;
#pragma unroll
        for (int tn = 0; tn < 4; tn++) {
            float2 v0, v1;
            v0.x = acc[tm][tn][0] + bias2[tn].x;
            v0.y = acc[tm][tn][1] + bias2[tn].y;
            v1.x = acc[tm][tn][2] + bias2[tn].x;
            v1.y = acc[tm][tn][3] + bias2[tn].y;
            *reinterpret_cast<float2*>(out + (size_t)rr * N_DIM + cols[tn])       = v0;
            *reinterpret_cast<float2*>(out + (size_t)(rr + 8) * N_DIM + cols[tn]) = v1;
        }
    }
}

// ---------------------------------------------------------------------------
extern "C" void kernel_launch(void* const* d_in, const int* in_sizes, int n_in,
                              void* d_out, int out_size) {
    const float* x = (const float*)d_in[0];
    const float* W = (const float*)d_in[1];
    const float* b = (const float*)d_in[2];
    float* out = (float*)d_out;

    const int n4 = (N_DIM * N_DIM) / 4;
    prep_kernel<<<(n4 + 255) / 256, 256>>>((const float4*)x, (const float4*)W, n4);

    cudaFuncSetAttribute(gemm_kernel, cudaFuncAttributeMaxDynamicSharedMemorySize,
                         SMEM_BYTES);
    dim3 grid(N_DIM / NTILE, N_DIM / MTILE);  // (32, 32)
    gemm_kernel<<<grid, 256, SMEM_BYTES>>>(b, out);
}

// round 6
// speedup vs baseline: 1.9889x; 1.9889x over previous
#include <cuda_runtime.h>
#include <cuda_fp16.h>
#include <cstdint>

// out[n,o] = sum_i x[n,i] * sign(W[o,i]) + b[o],  N=IN=OUT=4096, fp32 in/out.
//
// Legacy HMMA (tcgen05 not emittable at compute_103). f32-accumulate mma.sync
// (round-5 evidence: f16-acc gains nothing; tensor-active floor ~226us).
// Round-6 change: 64x64 warp tiles (A reuse 8x, B 4x -> 128B/HMMA) to get smem
// crossbar (was 128B/cyc, at limit) off the critical path. CTA 128x128, 4 warps,
// K-tile 64, 3-stage cp.async, XOR swizzle (conflict-free ldmatrix), 2 CTAs/SM.

#define N_DIM 4096
constexpr int MTILE = 128;
constexpr int NTILE = 128;
constexpr int KTILE = 64;
constexpr int NKT = N_DIM / KTILE;           // 64
constexpr int STAGE_BYTES = 2 * 128 * 128;   // A 16KB + B 16KB
constexpr int SMEM_BYTES = 3 * STAGE_BYTES;  // 98304

__device__ __half g_xh[(size_t)N_DIM * N_DIM];
__device__ __half g_wb[(size_t)N_DIM * N_DIM];

// ---------------------------------------------------------------------------
// prep: binarize W -> fp16, cast x -> fp16
// ---------------------------------------------------------------------------
__global__ void prep_kernel(const float4* __restrict__ x,
                            const float4* __restrict__ W, int n4) {
    int i = blockIdx.x * blockDim.x + threadIdx.x;
    if (i >= n4) return;
    float4 xv = x[i];
    float4 wv = W[i];
    float xs[4] = {xv.x, xv.y, xv.z, xv.w};
    float ws[4] = {wv.x, wv.y, wv.z, wv.w};
    alignas(8) __half xh[4], wb[4];
#pragma unroll
    for (int j = 0; j < 4; j++) {
        xh[j] = __float2half_rn(xs[j]);
        float s = (ws[j] > 0.0f) ? 1.0f : ((ws[j] < 0.0f) ? -1.0f : 0.0f);
        wb[j] = __float2half_rn(s);
    }
    size_t base = (size_t)i * 4;
    *reinterpret_cast<uint2*>(g_xh + base) = *reinterpret_cast<uint2*>(xh);
    *reinterpret_cast<uint2*>(g_wb + base) = *reinterpret_cast<uint2*>(wb);
}

// ---------------------------------------------------------------------------
// PTX helpers
// ---------------------------------------------------------------------------
__device__ __forceinline__ void cp16(uint32_t smem_addr, const void* gmem_ptr) {
    asm volatile("cp.async.cg.shared.global [%0], [%1], 16;\n"
                 :: "r"(smem_addr), "l"(gmem_ptr) : "memory");
}

__device__ __forceinline__ void ldsm_x4(uint32_t* r, uint32_t a) {
    asm volatile("ldmatrix.sync.aligned.m8n8.x4.shared.b16 {%0,%1,%2,%3}, [%4];\n"
                 : "=r"(r[0]), "=r"(r[1]), "=r"(r[2]), "=r"(r[3]) : "r"(a));
}

__device__ __forceinline__ void mma16816(float* d, const uint32_t* a,
                                         const uint32_t* b) {
    asm volatile("mma.sync.aligned.m16n8k16.row.col.f32.f16.f16.f32 "
                 "{%0,%1,%2,%3},{%4,%5,%6,%7},{%8,%9},{%0,%1,%2,%3};\n"
                 : "+f"(d[0]), "+f"(d[1]), "+f"(d[2]), "+f"(d[3])
                 : "r"(a[0]), "r"(a[1]), "r"(a[2]), "r"(a[3]),
                   "r"(b[0]), "r"(b[1]));
}

// ---------------------------------------------------------------------------
// GEMM: 128 threads = 4 warps in 2(M) x 2(N), warp tile 64x64.
// Stage layout: A rows 0-127, 128B/row XOR-swizzled; B at +16384 same.
// Swizzle: byte_off(row, ch16) = row*128 + ((ch16 ^ (row&7)) << 4)
// ---------------------------------------------------------------------------
__global__ void __launch_bounds__(128, 2)
gemm_kernel(const float* __restrict__ bias, float* __restrict__ out) {
    extern __shared__ char smem[];
    const uint32_t smem_base = (uint32_t)__cvta_generic_to_shared(smem);
    const int tid   = threadIdx.x;
    const int lane  = tid & 31;
    const int warp  = tid >> 5;
    const int warpM = warp & 1;
    const int warpN = warp >> 1;
    const int mBase = blockIdx.y * MTILE;
    const int nBase = blockIdx.x * NTILE;

    float acc[4][8][4];
#pragma unroll
    for (int a = 0; a < 4; a++)
#pragma unroll
        for (int b = 0; b < 8; b++)
#pragma unroll
            for (int c = 0; c < 4; c++) acc[a][b][c] = 0.0f;

    // ---- cp.async per-thread mapping: ch16 = tid&7, rows rbase + p*16 ----
    const int rbase = tid >> 3;               // 0..15
    const int ch    = tid & 7;
    const uint32_t swA = (uint32_t)rbase * 128 + (uint32_t)((ch ^ (rbase & 7)) << 4);
    const __half* gA = g_xh + (size_t)(mBase + rbase) * N_DIM + ch * 8;
    const __half* gB = g_wb + (size_t)(nBase + rbase) * N_DIM + ch * 8;

    auto prefetch = [&](int kt) {
        const uint32_t sb = smem_base + (uint32_t)(kt % 3) * STAGE_BYTES;
        const int k0 = kt * KTILE;
#pragma unroll
        for (int p = 0; p < 8; p++) {
            uint32_t so = swA + (uint32_t)p * 2048;      // +16 rows
            size_t go = (size_t)p * 16 * N_DIM + k0;
            cp16(sb + so,         gA + go);
            cp16(sb + 16384 + so, gB + go);
        }
        asm volatile("cp.async.commit_group;\n" ::: "memory");
    };

    // ---- ldmatrix per-thread row/offset precompute ----
    const uint32_t la7 = lane & 7;
    const uint32_t aHi = (lane >> 4) & 1;     // k +8 selector for A
    const uint32_t bHi = (lane >> 3) & 1;     // k +8 selector for B
    uint32_t aOff[4], bOff[4];
#pragma unroll
    for (int tm = 0; tm < 4; tm++) {
        uint32_t r = warpM * 64 + tm * 16 + (lane & 15);
        aOff[tm] = r * 128;
    }
#pragma unroll
    for (int pr = 0; pr < 4; pr++) {
        uint32_t r = warpN * 64 + pr * 16 + la7 + ((lane >> 4) & 1) * 8;
        bOff[pr] = 16384 + r * 128;
    }

    auto compute = [&](uint32_t sb) {
#pragma unroll
        for (int ks = 0; ks < 4; ks++) {
            const uint32_t ca = ((ks * 2 + aHi) ^ la7) << 4;
            const uint32_t cb = ((ks * 2 + bHi) ^ la7) << 4;
            uint32_t ah[4][4], bq[4][4];
#pragma unroll
            for (int tm = 0; tm < 4; tm++) ldsm_x4(ah[tm], sb + aOff[tm] + ca);
#pragma unroll
            for (int pr = 0; pr < 4; pr++) ldsm_x4(bq[pr], sb + bOff[pr] + cb);
#pragma unroll
            for (int tm = 0; tm < 4; tm++)
#pragma unroll
                for (int pr = 0; pr < 4; pr++) {
                    mma16816(acc[tm][2 * pr],     ah[tm], &bq[pr][0]);
                    mma16816(acc[tm][2 * pr + 1], ah[tm], &bq[pr][2]);
                }
        }
    };

    prefetch(0);
    prefetch(1);

    for (int kt = 0; kt < NKT; kt++) {
        if (kt + 1 < NKT)
            asm volatile("cp.async.wait_group 1;\n" ::: "memory");
        else
            asm volatile("cp.async.wait_group 0;\n" ::: "memory");
        __syncthreads();
        if (kt + 2 < NKT) prefetch(kt + 2);
        compute(smem_base + (uint32_t)(kt % 3) * STAGE_BYTES);
    }

    // ---- epilogue: + bias, fp32 store ----
    const int g  = lane >> 2;
    const int t4 = lane & 3;
    float2 bias2[8];
    int cols[8];
#pragma unroll
    for (int tn = 0; tn < 8; tn++) {
        cols[tn]  = nBase + warpN * 64 + tn * 8 + 2 * t4;
        bias2[tn] = *reinterpret_cast<const float2*>(bias + cols[tn]);
    }
#pragma unroll
    for (int tm = 0; tm < 4; tm++) {
        int rr = mBase + warpM * 64 + tm * 16 + g;
#pragma unroll
        for (int tn = 0; tn < 8; tn++) {
            float2 v0, v1;
            v0.x = acc[tm][tn][0] + bias2[tn].x;
            v0.y = acc[tm][tn][1] + bias2[tn].y;
            v1.x = acc[tm][tn][2] + bias2[tn].x;
            v1.y = acc[tm][tn][3] + bias2[tn].y;
            *reinterpret_cast<float2*>(out + (size_t)rr * N_DIM + cols[tn])       = v0;
            *reinterpret_cast<float2*>(out + (size_t)(rr + 8) * N_DIM + cols[tn]) = v1;
        }
    }
}

// ---------------------------------------------------------------------------
extern "C" void kernel_launch(void* const* d_in, const int* in_sizes, int n_in,
                              void* d_out, int out_size) {
    const float* x = (const float*)d_in[0];
    const float* W = (const float*)d_in[1];
    const float* b = (const float*)d_in[2];
    float* out = (float*)d_out;

    const int n4 = (N_DIM * N_DIM) / 4;
    prep_kernel<<<(n4 + 255) / 256, 256>>>((const float4*)x, (const float4*)W, n4);

    cudaFuncSetAttribute(gemm_kernel, cudaFuncAttributeMaxDynamicSharedMemorySize,
                         SMEM_BYTES);
    dim3 grid(N_DIM / NTILE, N_DIM / MTILE);  // (32, 32)
    gemm_kernel<<<grid, 128, SMEM_BYTES>>>(b, out);
}

// round 7
// speedup vs baseline: 2.0074x; 1.0093x over previous
#include <cuda_runtime.h>
#include <cuda_fp16.h>
#include <cstdint>

// out[n,o] = sum_i x[n,i] * sign(W[o,i]) + b[o],  N=IN=OUT=4096, fp32 in/out.
//
// Legacy HMMA f32-acc mma.sync (tcgen05 not emittable at compute_103).
// Round-6: 64x64 warp tiles fixed the smem-crossbar bind -> tensor 73.6%.
// Round-7: fill the remaining 26% issue holes with a 3rd CTA/SM:
//   2-stage pipeline (64KB smem/CTA), __launch_bounds__(128,3) (<=170 regs),
//   compute restructured to stream B fragments (low live-register set).

#define N_DIM 4096
constexpr int MTILE = 128;
constexpr int NTILE = 128;
constexpr int KTILE = 64;
constexpr int NKT = N_DIM / KTILE;           // 64
constexpr int STAGE_BYTES = 2 * 128 * 128;   // A 16KB + B 16KB
constexpr int SMEM_BYTES = 2 * STAGE_BYTES;  // 65536

__device__ __half g_xh[(size_t)N_DIM * N_DIM];
__device__ __half g_wb[(size_t)N_DIM * N_DIM];

// ---------------------------------------------------------------------------
// prep: binarize W -> fp16, cast x -> fp16
// ---------------------------------------------------------------------------
__global__ void prep_kernel(const float4* __restrict__ x,
                            const float4* __restrict__ W, int n4) {
    int i = blockIdx.x * blockDim.x + threadIdx.x;
    if (i >= n4) return;
    float4 xv = x[i];
    float4 wv = W[i];
    float xs[4] = {xv.x, xv.y, xv.z, xv.w};
    float ws[4] = {wv.x, wv.y, wv.z, wv.w};
    alignas(8) __half xh[4], wb[4];
#pragma unroll
    for (int j = 0; j < 4; j++) {
        xh[j] = __float2half_rn(xs[j]);
        float s = (ws[j] > 0.0f) ? 1.0f : ((ws[j] < 0.0f) ? -1.0f : 0.0f);
        wb[j] = __float2half_rn(s);
    }
    size_t base = (size_t)i * 4;
    *reinterpret_cast<uint2*>(g_xh + base) = *reinterpret_cast<uint2*>(xh);
    *reinterpret_cast<uint2*>(g_wb + base) = *reinterpret_cast<uint2*>(wb);
}

// ---------------------------------------------------------------------------
// PTX helpers
// ---------------------------------------------------------------------------
__device__ __forceinline__ void cp16(uint32_t smem_addr, const void* gmem_ptr) {
    asm volatile("cp.async.cg.shared.global [%0], [%1], 16;\n"
                 :: "r"(smem_addr), "l"(gmem_ptr) : "memory");
}

__device__ __forceinline__ void ldsm_x4(uint32_t* r, uint32_t a) {
    asm volatile("ldmatrix.sync.aligned.m8n8.x4.shared.b16 {%0,%1,%2,%3}, [%4];\n"
                 : "=r"(r[0]), "=r"(r[1]), "=r"(r[2]), "=r"(r[3]) : "r"(a));
}

__device__ __forceinline__ void mma16816(float* d, const uint32_t* a,
                                         const uint32_t* b) {
    asm volatile("mma.sync.aligned.m16n8k16.row.col.f32.f16.f16.f32 "
                 "{%0,%1,%2,%3},{%4,%5,%6,%7},{%8,%9},{%0,%1,%2,%3};\n"
                 : "+f"(d[0]), "+f"(d[1]), "+f"(d[2]), "+f"(d[3])
                 : "r"(a[0]), "r"(a[1]), "r"(a[2]), "r"(a[3]),
                   "r"(b[0]), "r"(b[1]));
}

// ---------------------------------------------------------------------------
// GEMM: 128 threads = 4 warps in 2(M) x 2(N), warp tile 64x64.
// Stage layout: A rows 0-127 (128B/row XOR-swizzled), B at +16384 same.
// Swizzle: byte_off(row, ch16) = row*128 + ((ch16 ^ (row&7)) << 4)
// ---------------------------------------------------------------------------
__global__ void __launch_bounds__(128, 3)
gemm_kernel(const float* __restrict__ bias, float* __restrict__ out) {
    extern __shared__ char smem[];
    const uint32_t smem_base = (uint32_t)__cvta_generic_to_shared(smem);
    const int tid   = threadIdx.x;
    const int lane  = tid & 31;
    const int warp  = tid >> 5;
    const int warpM = warp & 1;
    const int warpN = warp >> 1;
    const int mBase = blockIdx.y * MTILE;
    const int nBase = blockIdx.x * NTILE;

    float acc[4][8][4];
#pragma unroll
    for (int a = 0; a < 4; a++)
#pragma unroll
        for (int b = 0; b < 8; b++)
#pragma unroll
            for (int c = 0; c < 4; c++) acc[a][b][c] = 0.0f;

    // ---- cp.async per-thread mapping: ch16 = tid&7, rows rbase + p*16 ----
    const int rbase = tid >> 3;               // 0..15
    const int ch    = tid & 7;
    const uint32_t swA = (uint32_t)rbase * 128 + (uint32_t)((ch ^ (rbase & 7)) << 4);
    const __half* gA = g_xh + (size_t)(mBase + rbase) * N_DIM + ch * 8;
    const __half* gB = g_wb + (size_t)(nBase + rbase) * N_DIM + ch * 8;

    auto prefetch = [&](int kt) {
        const uint32_t sb = smem_base + (uint32_t)(kt & 1) * STAGE_BYTES;
        const int k0 = kt * KTILE;
#pragma unroll
        for (int p = 0; p < 8; p++) {
            uint32_t so = swA + (uint32_t)p * 2048;      // +16 rows
            size_t go = (size_t)p * 16 * N_DIM + k0;
            cp16(sb + so,         gA + go);
            cp16(sb + 16384 + so, gB + go);
        }
        asm volatile("cp.async.commit_group;\n" ::: "memory");
    };

    // ---- ldmatrix per-thread row/offset precompute ----
    const uint32_t la7 = lane & 7;
    const uint32_t aHi = (lane >> 4) & 1;     // k +8 selector for A
    const uint32_t bHi = (lane >> 3) & 1;     // k +8 selector for B
    uint32_t aOff[4], bOff[4];
#pragma unroll
    for (int tm = 0; tm < 4; tm++) {
        uint32_t r = warpM * 64 + tm * 16 + (lane & 15);
        aOff[tm] = r * 128;
    }
#pragma unroll
    for (int pr = 0; pr < 4; pr++) {
        uint32_t r = warpN * 64 + pr * 16 + la7 + ((lane >> 4) & 1) * 8;
        bOff[pr] = 16384 + r * 128;
    }

    // compute one k-tile; B fragments streamed to keep live registers low
    auto compute = [&](uint32_t sb) {
#pragma unroll
        for (int ks = 0; ks < 4; ks++) {
            const uint32_t ca = ((ks * 2 + aHi) ^ la7) << 4;
            const uint32_t cb = ((ks * 2 + bHi) ^ la7) << 4;
            uint32_t ah[4][4];
#pragma unroll
            for (int tm = 0; tm < 4; tm++) ldsm_x4(ah[tm], sb + aOff[tm] + ca);
#pragma unroll
            for (int pr = 0; pr < 4; pr++) {
                uint32_t bq[4];
                ldsm_x4(bq, sb + bOff[pr] + cb);
#pragma unroll
                for (int tm = 0; tm < 4; tm++) {
                    mma16816(acc[tm][2 * pr],     ah[tm], &bq[0]);
                    mma16816(acc[tm][2 * pr + 1], ah[tm], &bq[2]);
                }
            }
        }
    };

    prefetch(0);

    for (int kt = 0; kt < NKT; kt++) {
        asm volatile("cp.async.wait_group 0;\n" ::: "memory");
        __syncthreads();
        if (kt + 1 < NKT) prefetch(kt + 1);
        compute(smem_base + (uint32_t)(kt & 1) * STAGE_BYTES);
    }

    // ---- epilogue: + bias, fp32 store ----
    const int g  = lane >> 2;
    const int t4 = lane & 3;
#pragma unroll
    for (int tm = 0; tm < 4; tm++) {
        int rr = mBase + warpM * 64 + tm * 16 + g;
#pragma unroll
        for (int tn = 0; tn < 8; tn++) {
            int col = nBase + warpN * 64 + tn * 8 + 2 * t4;
            float2 b2 = *reinterpret_cast<const float2*>(bias + col);
            float2 v0, v1;
            v0.x = acc[tm][tn][0] + b2.x;
            v0.y = acc[tm][tn][1] + b2.y;
            v1.x = acc[tm][tn][2] + b2.x;
            v1.y = acc[tm][tn][3] + b2.y;
            *reinterpret_cast<float2*>(out + (size_t)rr * N_DIM + col)       = v0;
            *reinterpret_cast<float2*>(out + (size_t)(rr + 8) * N_DIM + col) = v1;
        }
    }
}

// ---------------------------------------------------------------------------
extern "C" void kernel_launch(void* const* d_in, const int* in_sizes, int n_in,
                              void* d_out, int out_size) {
    const float* x = (const float*)d_in[0];
    const float* W = (const float*)d_in[1];
    const float* b = (const float*)d_in[2];
    float* out = (float*)d_out;

    const int n4 = (N_DIM * N_DIM) / 4;
    prep_kernel<<<(n4 + 255) / 256, 256>>>((const float4*)x, (const float4*)W, n4);

    cudaFuncSetAttribute(gemm_kernel, cudaFuncAttributeMaxDynamicSharedMemorySize,
                         SMEM_BYTES);
    dim3 grid(N_DIM / NTILE, N_DIM / MTILE);  // (32, 32)
    gemm_kernel<<<grid, 128, SMEM_BYTES>>>(b, out);
}